// round 2
// baseline (speedup 1.0000x reference)
#include <cuda_runtime.h>

#define NEMB 1024
#define HS 64
#define BB 8
#define TT 2048
#define BT (BB * TT)

#define PAD 68  // smem row stride (floats) for 64-wide padded tiles; %4==0 for float4

// Scratch for projected Q, K, V (allocation-free: __device__ globals)
__device__ float g_Q[BT * HS];
__device__ float g_K[BT * HS];
__device__ float g_V[BT * HS];

// ---------------------------------------------------------------------------
// Projection GEMM: C = X @ W   (X: BT x NEMB, W: NEMB x HS)
// BM=64, BN=64(=HS), KT=16. 256 threads as 16x16, each owns 4x4 microtile.
// blockIdx.y selects which of Wq/Wk/Wv (and target buffer).
// ---------------------------------------------------------------------------
__global__ __launch_bounds__(256) void proj_kernel(
    const float* __restrict__ x,
    const float* __restrict__ Wq,
    const float* __restrict__ Wk,
    const float* __restrict__ Wv)
{
    __shared__ float Xs[64][20];   // 64 rows x 16 k (pad 20 for alignment)
    __shared__ float Ws[16][64];   // 16 k x 64 n

    const float* W = (blockIdx.y == 0) ? Wq : (blockIdx.y == 1) ? Wk : Wv;
    float* C = (blockIdx.y == 0) ? g_Q : (blockIdx.y == 1) ? g_K : g_V;

    const int bt0 = blockIdx.x * 64;
    const int tid = threadIdx.x;
    const int tx = tid & 15;
    const int ty = tid >> 4;

    // loader indices
    const int xr = tid >> 2;            // 0..63
    const int xc = (tid & 3) * 4;       // 0,4,8,12
    const int wk = tid >> 4;            // 0..15
    const int wn = (tid & 15) * 4;      // 0..60

    float acc[4][4] = {};

    for (int kt = 0; kt < NEMB / 16; ++kt) {
        // load X tile 64x16 (float4, coalesced)
        float4 xv = *(const float4*)&x[(size_t)(bt0 + xr) * NEMB + kt * 16 + xc];
        *(float4*)&Xs[xr][xc] = xv;
        // load W tile 16x64 (float4, coalesced)
        float4 wv = *(const float4*)&W[(size_t)(kt * 16 + wk) * HS + wn];
        *(float4*)&Ws[wk][wn] = wv;
        __syncthreads();

        #pragma unroll
        for (int k4 = 0; k4 < 4; ++k4) {
            float a[4][4];   // [i][kk]
            float b[4][4];   // [kk][j]
            #pragma unroll
            for (int i = 0; i < 4; ++i) {
                float4 t = *(const float4*)&Xs[ty + 16 * i][k4 * 4];
                a[i][0] = t.x; a[i][1] = t.y; a[i][2] = t.z; a[i][3] = t.w;
            }
            #pragma unroll
            for (int kk = 0; kk < 4; ++kk) {
                float4 t = *(const float4*)&Ws[k4 * 4 + kk][tx * 4];
                b[kk][0] = t.x; b[kk][1] = t.y; b[kk][2] = t.z; b[kk][3] = t.w;
            }
            #pragma unroll
            for (int i = 0; i < 4; ++i)
                #pragma unroll
                for (int j = 0; j < 4; ++j)
                    #pragma unroll
                    for (int kk = 0; kk < 4; ++kk)
                        acc[i][j] += a[i][kk] * b[kk][j];
        }
        __syncthreads();
    }

    #pragma unroll
    for (int i = 0; i < 4; ++i) {
        float4 o;
        o.x = acc[i][0]; o.y = acc[i][1]; o.z = acc[i][2]; o.w = acc[i][3];
        *(float4*)&C[(size_t)(bt0 + ty + 16 * i) * HS + tx * 4] = o;
    }
}

// ---------------------------------------------------------------------------
// Fused causal attention with online softmax (flash-style), fp32.
// One CTA per (batch, 64-query tile). 256 threads as 16x16.
//   S GEMM mapping:  row = ty+16i (query), col = tx+16j (key)
//   PV/out mapping:  row = ty+16i (query), dim = tx*4+j  (head dim)
// Row-group softmax reductions happen across the 16 tx-lanes (shfl_xor 8/4/2/1).
// ---------------------------------------------------------------------------
__global__ __launch_bounds__(256) void attn_kernel(float* __restrict__ out)
{
    extern __shared__ float sm[];
    float* Qs = sm;                    // 64 x PAD
    float* Ks = sm + 64 * PAD;         // 64 x PAD
    float* Ps = sm + 2 * 64 * PAD;     // 64 x PAD
    float* Vs = sm + 3 * 64 * PAD;     // 64 x 64 (unpadded)

    const int b  = blockIdx.y;
    const int qt = gridDim.x - 1 - blockIdx.x;   // heavy tiles first
    const int t0 = qt * 64;
    const int tid = threadIdx.x;
    const int tx = tid & 15;
    const int ty = tid >> 4;

    const float NEG_INF = -1e30f;

    // Load Q tile (contiguous 4096 floats)
    {
        const float4* Qg = (const float4*)(g_Q + (size_t)(b * TT + t0) * HS);
        #pragma unroll
        for (int r = 0; r < 4; ++r) {
            int idx = tid + 256 * r;
            int row = idx >> 4;
            int c   = (idx & 15) * 4;
            *(float4*)&Qs[row * PAD + c] = Qg[idx];
        }
    }

    float acc[4][4] = {};
    float m[4], l[4];
    #pragma unroll
    for (int i = 0; i < 4; ++i) { m[i] = NEG_INF; l[i] = 0.0f; }

    for (int kt = 0; kt <= qt; ++kt) {
        __syncthreads();  // protect K/V/P from readers of the previous iteration

        // Load K and V tiles (each contiguous 4096 floats)
        {
            const float4* Kg = (const float4*)(g_K + (size_t)(b * TT + kt * 64) * HS);
            const float4* Vg = (const float4*)(g_V + (size_t)(b * TT + kt * 64) * HS);
            #pragma unroll
            for (int r = 0; r < 4; ++r) {
                int idx = tid + 256 * r;
                int row = idx >> 4;
                int c   = (idx & 15) * 4;
                *(float4*)&Ks[row * PAD + c] = Kg[idx];
                *(float4*)&Vs[row * 64 + c]  = Vg[idx];
            }
        }
        __syncthreads();

        // S = Q K^T (64x64x64), per-thread 4x4 at (ty+16i, tx+16j)
        float s[4][4] = {};
        #pragma unroll
        for (int h4 = 0; h4 < 16; ++h4) {
            float a[4][4];   // [i][hh]
            float kx[4][4];  // [j][hh]
            #pragma unroll
            for (int i = 0; i < 4; ++i) {
                float4 t = *(const float4*)&Qs[(ty + 16 * i) * PAD + h4 * 4];
                a[i][0] = t.x; a[i][1] = t.y; a[i][2] = t.z; a[i][3] = t.w;
            }
            #pragma unroll
            for (int j = 0; j < 4; ++j) {
                float4 t = *(const float4*)&Ks[(tx + 16 * j) * PAD + h4 * 4];
                kx[j][0] = t.x; kx[j][1] = t.y; kx[j][2] = t.z; kx[j][3] = t.w;
            }
            #pragma unroll
            for (int i = 0; i < 4; ++i)
                #pragma unroll
                for (int j = 0; j < 4; ++j)
                    #pragma unroll
                    for (int hh = 0; hh < 4; ++hh)
                        s[i][j] += a[i][hh] * kx[j][hh];
        }

        // Causal mask (only diagonal tile needs it)
        if (kt == qt) {
            #pragma unroll
            for (int i = 0; i < 4; ++i)
                #pragma unroll
                for (int j = 0; j < 4; ++j)
                    if ((tx + 16 * j) > (ty + 16 * i)) s[i][j] = NEG_INF;
        }

        // Online softmax update + write P
        #pragma unroll
        for (int i = 0; i < 4; ++i) {
            float mx = fmaxf(fmaxf(s[i][0], s[i][1]), fmaxf(s[i][2], s[i][3]));
            #pragma unroll
            for (int off = 8; off >= 1; off >>= 1)
                mx = fmaxf(mx, __shfl_xor_sync(0xffffffffu, mx, off));
            float mnew  = fmaxf(m[i], mx);
            float alpha = __expf(m[i] - mnew);
            float sum = 0.0f;
            #pragma unroll
            for (int j = 0; j < 4; ++j) {
                float p = __expf(s[i][j] - mnew);
                Ps[(ty + 16 * i) * PAD + tx + 16 * j] = p;
                sum += p;
            }
            #pragma unroll
            for (int off = 8; off >= 1; off >>= 1)
                sum += __shfl_xor_sync(0xffffffffu, sum, off);
            l[i] = l[i] * alpha + sum;
            m[i] = mnew;
            #pragma unroll
            for (int j = 0; j < 4; ++j) acc[i][j] *= alpha;
        }
        __syncthreads();

        // acc += P @ V  (64x64x64), per-thread 4x4 at (ty+16i, tx*4+j)
        #pragma unroll
        for (int s4 = 0; s4 < 16; ++s4) {
            float p[4][4];   // [i][ss]
            float v[4][4];   // [ss][j]
            #pragma unroll
            for (int i = 0; i < 4; ++i) {
                float4 t = *(const float4*)&Ps[(ty + 16 * i) * PAD + s4 * 4];
                p[i][0] = t.x; p[i][1] = t.y; p[i][2] = t.z; p[i][3] = t.w;
            }
            #pragma unroll
            for (int ss = 0; ss < 4; ++ss) {
                float4 t = *(const float4*)&Vs[(s4 * 4 + ss) * 64 + tx * 4];
                v[ss][0] = t.x; v[ss][1] = t.y; v[ss][2] = t.z; v[ss][3] = t.w;
            }
            #pragma unroll
            for (int i = 0; i < 4; ++i)
                #pragma unroll
                for (int j = 0; j < 4; ++j)
                    #pragma unroll
                    for (int ss = 0; ss < 4; ++ss)
                        acc[i][j] += p[i][ss] * v[ss][j];
        }
    }

    // Epilogue: out = acc / l
    #pragma unroll
    for (int i = 0; i < 4; ++i) {
        float inv = 1.0f / l[i];
        float4 o;
        o.x = acc[i][0] * inv; o.y = acc[i][1] * inv;
        o.z = acc[i][2] * inv; o.w = acc[i][3] * inv;
        *(float4*)&out[(size_t)(b * TT + t0 + ty + 16 * i) * HS + tx * 4] = o;
    }
}

// ---------------------------------------------------------------------------

static const int ATTN_SMEM = (3 * 64 * PAD + 64 * 64) * (int)sizeof(float);  // 68608 B

extern "C" void kernel_launch(void* const* d_in, const int* in_sizes, int n_in,
                              void* d_out, int out_size)
{
    const float* x  = (const float*)d_in[0];
    const float* Wq = (const float*)d_in[1];
    const float* Wk = (const float*)d_in[2];
    const float* Wv = (const float*)d_in[3];
    float* out = (float*)d_out;

    (void)in_sizes; (void)n_in; (void)out_size;

    cudaFuncSetAttribute(attn_kernel, cudaFuncAttributeMaxDynamicSharedMemorySize,
                         ATTN_SMEM);

    proj_kernel<<<dim3(BT / 64, 3), 256>>>(x, Wq, Wk, Wv);
    attn_kernel<<<dim3(TT / 64, BB), 256, ATTN_SMEM>>>(out);
}

// round 3
// speedup vs baseline: 2.8338x; 2.8338x over previous
#include <cuda_runtime.h>
#include <cuda_bf16.h>

#define NEMB 1024
#define HS 64
#define BB 8
#define TT 2048
#define BT (BB*TT)
#define LDB 72          // smem row stride in bf16 (144B: conflict-free ldmatrix)
#define NQT (TT/64)     // 32 query tiles per batch

__device__ __align__(16) __nv_bfloat16 gQh[BT*HS];
__device__ __align__(16) __nv_bfloat16 gQl[BT*HS];
__device__ __align__(16) __nv_bfloat16 gKh[BT*HS];
__device__ __align__(16) __nv_bfloat16 gKl[BT*HS];
__device__ __align__(16) __nv_bfloat16 gVh[BT*HS];
__device__ __align__(16) __nv_bfloat16 gVl[BT*HS];

__device__ __forceinline__ unsigned su32(const void* p) {
    return (unsigned)__cvta_generic_to_shared(p);
}
__device__ __forceinline__ void ldsm4(unsigned a, unsigned* r) {
    asm volatile("ldmatrix.sync.aligned.m8n8.x4.shared.b16 {%0,%1,%2,%3},[%4];\n"
                 : "=r"(r[0]), "=r"(r[1]), "=r"(r[2]), "=r"(r[3]) : "r"(a));
}
__device__ __forceinline__ void ldsm4t(unsigned a, unsigned* r) {
    asm volatile("ldmatrix.sync.aligned.m8n8.x4.trans.shared.b16 {%0,%1,%2,%3},[%4];\n"
                 : "=r"(r[0]), "=r"(r[1]), "=r"(r[2]), "=r"(r[3]) : "r"(a));
}
__device__ __forceinline__ void mma16816(float* c, const unsigned* a, unsigned b0, unsigned b1) {
    asm volatile("mma.sync.aligned.m16n8k16.row.col.f32.bf16.bf16.f32 "
                 "{%0,%1,%2,%3},{%4,%5,%6,%7},{%8,%9},{%0,%1,%2,%3};\n"
                 : "+f"(c[0]), "+f"(c[1]), "+f"(c[2]), "+f"(c[3])
                 : "r"(a[0]), "r"(a[1]), "r"(a[2]), "r"(a[3]), "r"(b0), "r"(b1));
}
// split two floats into packed-bf16 hi and lo (residual) registers
__device__ __forceinline__ void splitp(float x, float y, unsigned& h, unsigned& l) {
    __nv_bfloat162 hh = __floats2bfloat162_rn(x, y);
    float2 f = __bfloat1622float2(hh);
    __nv_bfloat162 ll = __floats2bfloat162_rn(x - f.x, y - f.y);
    h = *(unsigned*)&hh; l = *(unsigned*)&ll;
}
__device__ __forceinline__ void split4s(float4 v, __nv_bfloat16* dh, __nv_bfloat16* dl) {
    unsigned h0, l0, h1, l1;
    splitp(v.x, v.y, h0, l0); splitp(v.z, v.w, h1, l1);
    uint2 hv = make_uint2(h0, h1), lv = make_uint2(l0, l1);
    *(uint2*)dh = hv; *(uint2*)dl = lv;
}

// ---------------------------------------------------------------------------
// Projection: one CTA = 64 rows of X, computes Q,K,V (bf16x3 MMA), outputs
// hi/lo bf16 pairs. 8 warps: 4 m-groups x 2 n-groups(32 cols).
// ---------------------------------------------------------------------------
__global__ __launch_bounds__(256) void proj_kernel(
    const float* __restrict__ x, const float* __restrict__ Wq,
    const float* __restrict__ Wk, const float* __restrict__ Wv)
{
    extern __shared__ char smc[];
    __nv_bfloat16* sXh = (__nv_bfloat16*)smc;       // 64*LDB
    __nv_bfloat16* sXl = sXh + 64*LDB;
    __nv_bfloat16* sWh = sXl + 64*LDB;              // 3 mats x 64*LDB
    __nv_bfloat16* sWl = sWh + 3*64*LDB;

    const float* Wsrc[3] = {Wq, Wk, Wv};
    const int bt0 = blockIdx.x * 64;
    const int tid = threadIdx.x, lane = tid & 31, wid = tid >> 5;
    const int wm = wid & 3, wn = wid >> 2;

    float acc[3][4][4];
    #pragma unroll
    for (int m = 0; m < 3; ++m)
        #pragma unroll
        for (int t = 0; t < 4; ++t)
            #pragma unroll
            for (int r = 0; r < 4; ++r) acc[m][t][r] = 0.f;

    for (int kt = 0; kt < NEMB/64; ++kt) {
        __syncthreads();
        // X tile 64x64: 4 float4 per thread
        #pragma unroll
        for (int r = 0; r < 4; ++r) {
            int u = tid + 256*r, row = u >> 4, c = (u & 15) * 4;
            float4 v = *(const float4*)&x[(size_t)(bt0+row)*NEMB + kt*64 + c];
            split4s(v, &sXh[row*LDB+c], &sXl[row*LDB+c]);
        }
        // W tiles (3x 64x64): 12 float4 per thread
        #pragma unroll
        for (int r = 0; r < 12; ++r) {
            int u = tid + 256*r, mat = u >> 10, w = u & 1023;
            int row = w >> 4, c = (w & 15) * 4;
            float4 v = *(const float4*)&Wsrc[mat][(size_t)(kt*64+row)*HS + c];
            split4s(v, &sWh[mat*64*LDB + row*LDB + c], &sWl[mat*64*LDB + row*LDB + c]);
        }
        __syncthreads();

        #pragma unroll
        for (int kk = 0; kk < 4; ++kk) {
            unsigned ah[4], al[4];
            unsigned ao = (unsigned)(((wm*16 + (lane&15))*LDB + kk*16 + (lane>>4)*8) * 2);
            ldsm4(su32(sXh) + ao, ah);
            ldsm4(su32(sXl) + ao, al);
            #pragma unroll
            for (int mat = 0; mat < 3; ++mat) {
                #pragma unroll
                for (int nb = 0; nb < 2; ++nb) {
                    unsigned bh[4], bl[4];
                    unsigned bo = (unsigned)((mat*64*LDB + (kk*16 + (lane&15))*LDB +
                                              wn*32 + nb*16 + (lane>>4)*8) * 2);
                    ldsm4t(su32(sWh) + bo, bh);
                    ldsm4t(su32(sWl) + bo, bl);
                    float* c0 = acc[mat][nb*2]; float* c1 = acc[mat][nb*2+1];
                    mma16816(c0, ah, bh[0], bh[1]);
                    mma16816(c0, ah, bl[0], bl[1]);
                    mma16816(c0, al, bh[0], bh[1]);
                    mma16816(c1, ah, bh[2], bh[3]);
                    mma16816(c1, ah, bl[2], bl[3]);
                    mma16816(c1, al, bh[2], bh[3]);
                }
            }
        }
    }

    __nv_bfloat16* const GH[3] = {gQh, gKh, gVh};
    __nv_bfloat16* const GL[3] = {gQl, gKl, gVl};
    const int r0 = bt0 + wm*16 + (lane >> 2);
    #pragma unroll
    for (int mat = 0; mat < 3; ++mat)
        #pragma unroll
        for (int nt = 0; nt < 4; ++nt) {
            int col = wn*32 + nt*8 + 2*(lane & 3);
            unsigned h, l;
            splitp(acc[mat][nt][0], acc[mat][nt][1], h, l);
            *(unsigned*)&GH[mat][(size_t)r0*HS + col] = h;
            *(unsigned*)&GL[mat][(size_t)r0*HS + col] = l;
            splitp(acc[mat][nt][2], acc[mat][nt][3], h, l);
            *(unsigned*)&GH[mat][(size_t)(r0+8)*HS + col] = h;
            *(unsigned*)&GL[mat][(size_t)(r0+8)*HS + col] = l;
        }
}

// ---------------------------------------------------------------------------
// Flash attention, bf16x3 MMA. CTA j of batch b handles query tiles j and
// NQT-1-j (balanced). 4 warps; warp w owns query rows w*16..w*16+15.
// ---------------------------------------------------------------------------
__global__ __launch_bounds__(128) void attn_kernel(float* __restrict__ out)
{
    extern __shared__ char smc[];
    __nv_bfloat16* sQh = (__nv_bfloat16*)smc;
    __nv_bfloat16* sQl = sQh + 64*LDB;
    __nv_bfloat16* sKh = sQl + 64*LDB;
    __nv_bfloat16* sKl = sKh + 64*LDB;
    __nv_bfloat16* sVh = sKl + 64*LDB;
    __nv_bfloat16* sVl = sVh + 64*LDB;

    const int b = blockIdx.y;
    const int tid = threadIdx.x, lane = tid & 31, w = tid >> 5;
    const int lr = lane >> 2;                 // row-in-8 group
    const int lc2 = 2 * (lane & 3);           // col pair base

    #pragma unroll
    for (int pass = 0; pass < 2; ++pass) {
        const int qt = pass ? (NQT - 1 - blockIdx.x) : blockIdx.x;
        const int t0 = qt * 64;

        __syncthreads();  // previous pass readers done
        // load Q tile hi/lo (uint4 = 8 bf16)
        #pragma unroll
        for (int r = 0; r < 4; ++r) {
            int u = tid + 128*r, row = u >> 3, c = (u & 7) * 8;
            size_t g = (size_t)(b*TT + t0 + row) * HS + c;
            *(uint4*)&sQh[row*LDB + c] = *(const uint4*)&gQh[g];
            *(uint4*)&sQl[row*LDB + c] = *(const uint4*)&gQl[g];
        }
        __syncthreads();
        unsigned qh[4][4], ql[4][4];
        #pragma unroll
        for (int kk = 0; kk < 4; ++kk) {
            unsigned ao = (unsigned)(((w*16 + (lane&15))*LDB + kk*16 + (lane>>4)*8) * 2);
            ldsm4(su32(sQh) + ao, qh[kk]);
            ldsm4(su32(sQl) + ao, ql[kk]);
        }

        float o[8][4];
        #pragma unroll
        for (int t = 0; t < 8; ++t)
            #pragma unroll
            for (int r = 0; r < 4; ++r) o[t][r] = 0.f;
        float m0 = -1e30f, m1 = -1e30f, l0 = 0.f, l1 = 0.f;

        for (int kt = 0; kt <= qt; ++kt) {
            __syncthreads();
            #pragma unroll
            for (int r = 0; r < 4; ++r) {
                int u = tid + 128*r, row = u >> 3, c = (u & 7) * 8;
                size_t g = (size_t)(b*TT + kt*64 + row) * HS + c;
                int s = row*LDB + c;
                *(uint4*)&sKh[s] = *(const uint4*)&gKh[g];
                *(uint4*)&sKl[s] = *(const uint4*)&gKl[g];
                *(uint4*)&sVh[s] = *(const uint4*)&gVh[g];
                *(uint4*)&sVl[s] = *(const uint4*)&gVl[g];
            }
            __syncthreads();

            // S = Q K^T  (bf16x3)
            float st[8][4];
            #pragma unroll
            for (int t = 0; t < 8; ++t)
                #pragma unroll
                for (int r = 0; r < 4; ++r) st[t][r] = 0.f;
            #pragma unroll
            for (int kk = 0; kk < 4; ++kk) {
                #pragma unroll
                for (int kb = 0; kb < 4; ++kb) {
                    unsigned kh[4], kl[4];
                    unsigned ko = (unsigned)(((kb*16 + (lane&15))*LDB + kk*16 + (lane>>4)*8) * 2);
                    ldsm4(su32(sKh) + ko, kh);
                    ldsm4(su32(sKl) + ko, kl);
                    float* c0 = st[kb*2]; float* c1 = st[kb*2+1];
                    mma16816(c0, qh[kk], kh[0], kh[2]);
                    mma16816(c0, qh[kk], kl[0], kl[2]);
                    mma16816(c0, ql[kk], kh[0], kh[2]);
                    mma16816(c1, qh[kk], kh[1], kh[3]);
                    mma16816(c1, qh[kk], kl[1], kl[3]);
                    mma16816(c1, ql[kk], kh[1], kh[3]);
                }
            }

            if (kt == qt) {
                int r0 = w*16 + lr, r1 = r0 + 8;
                #pragma unroll
                for (int nt = 0; nt < 8; ++nt) {
                    int c = nt*8 + lc2;
                    if (c     > r0) st[nt][0] = -1e30f;
                    if (c + 1 > r0) st[nt][1] = -1e30f;
                    if (c     > r1) st[nt][2] = -1e30f;
                    if (c + 1 > r1) st[nt][3] = -1e30f;
                }
            }

            // online softmax (rows within lane quads)
            float mx0 = -1e30f, mx1 = -1e30f;
            #pragma unroll
            for (int nt = 0; nt < 8; ++nt) {
                mx0 = fmaxf(mx0, fmaxf(st[nt][0], st[nt][1]));
                mx1 = fmaxf(mx1, fmaxf(st[nt][2], st[nt][3]));
            }
            mx0 = fmaxf(mx0, __shfl_xor_sync(0xffffffffu, mx0, 1));
            mx0 = fmaxf(mx0, __shfl_xor_sync(0xffffffffu, mx0, 2));
            mx1 = fmaxf(mx1, __shfl_xor_sync(0xffffffffu, mx1, 1));
            mx1 = fmaxf(mx1, __shfl_xor_sync(0xffffffffu, mx1, 2));
            float mn0 = fmaxf(m0, mx0), mn1 = fmaxf(m1, mx1);
            float a0 = __expf(m0 - mn0), a1 = __expf(m1 - mn1);
            float s0 = 0.f, s1 = 0.f;
            #pragma unroll
            for (int nt = 0; nt < 8; ++nt) {
                st[nt][0] = __expf(st[nt][0] - mn0);
                st[nt][1] = __expf(st[nt][1] - mn0);
                st[nt][2] = __expf(st[nt][2] - mn1);
                st[nt][3] = __expf(st[nt][3] - mn1);
                s0 += st[nt][0] + st[nt][1];
                s1 += st[nt][2] + st[nt][3];
            }
            s0 += __shfl_xor_sync(0xffffffffu, s0, 1);
            s0 += __shfl_xor_sync(0xffffffffu, s0, 2);
            s1 += __shfl_xor_sync(0xffffffffu, s1, 1);
            s1 += __shfl_xor_sync(0xffffffffu, s1, 2);
            l0 = l0 * a0 + s0; l1 = l1 * a1 + s1;
            m0 = mn0; m1 = mn1;
            #pragma unroll
            for (int nt = 0; nt < 8; ++nt) {
                o[nt][0] *= a0; o[nt][1] *= a0; o[nt][2] *= a1; o[nt][3] *= a1;
            }

            // P fragments (register repack, hi/lo)
            unsigned ph[4][4], pl[4][4];
            #pragma unroll
            for (int t = 0; t < 4; ++t) {
                splitp(st[2*t][0],   st[2*t][1],   ph[t][0], pl[t][0]);
                splitp(st[2*t][2],   st[2*t][3],   ph[t][1], pl[t][1]);
                splitp(st[2*t+1][0], st[2*t+1][1], ph[t][2], pl[t][2]);
                splitp(st[2*t+1][2], st[2*t+1][3], ph[t][3], pl[t][3]);
            }
            // O += P V  (bf16x3)
            #pragma unroll
            for (int t = 0; t < 4; ++t) {
                #pragma unroll
                for (int nb = 0; nb < 4; ++nb) {
                    unsigned vh[4], vl[4];
                    unsigned vo = (unsigned)(((t*16 + (lane&15))*LDB + nb*16 + (lane>>4)*8) * 2);
                    ldsm4t(su32(sVh) + vo, vh);
                    ldsm4t(su32(sVl) + vo, vl);
                    float* c0 = o[nb*2]; float* c1 = o[nb*2+1];
                    mma16816(c0, ph[t], vh[0], vh[1]);
                    mma16816(c0, ph[t], vl[0], vl[1]);
                    mma16816(c0, pl[t], vh[0], vh[1]);
                    mma16816(c1, ph[t], vh[2], vh[3]);
                    mma16816(c1, ph[t], vl[2], vl[3]);
                    mma16816(c1, pl[t], vh[2], vh[3]);
                }
            }
        }

        // epilogue
        float i0 = 1.f / l0, i1 = 1.f / l1;
        int gr0 = b*TT + t0 + w*16 + lr;
        #pragma unroll
        for (int nt = 0; nt < 8; ++nt) {
            int col = nt*8 + lc2;
            float2 v0 = make_float2(o[nt][0]*i0, o[nt][1]*i0);
            float2 v1 = make_float2(o[nt][2]*i1, o[nt][3]*i1);
            *(float2*)&out[(size_t)gr0*HS + col] = v0;
            *(float2*)&out[(size_t)(gr0+8)*HS + col] = v1;
        }
    }
}

// ---------------------------------------------------------------------------
static const int PROJ_SMEM = 8 * 64 * LDB * 2;   // 73728
static const int ATTN_SMEM = 6 * 64 * LDB * 2;   // 55296

extern "C" void kernel_launch(void* const* d_in, const int* in_sizes, int n_in,
                              void* d_out, int out_size)
{
    const float* x  = (const float*)d_in[0];
    const float* Wq = (const float*)d_in[1];
    const float* Wk = (const float*)d_in[2];
    const float* Wv = (const float*)d_in[3];
    float* out = (float*)d_out;
    (void)in_sizes; (void)n_in; (void)out_size;

    cudaFuncSetAttribute(proj_kernel, cudaFuncAttributeMaxDynamicSharedMemorySize, PROJ_SMEM);
    cudaFuncSetAttribute(attn_kernel, cudaFuncAttributeMaxDynamicSharedMemorySize, ATTN_SMEM);

    proj_kernel<<<BT/64, 256, PROJ_SMEM>>>(x, Wq, Wk, Wv);
    attn_kernel<<<dim3(NQT/2, BB), 128, ATTN_SMEM>>>(out);
}